// round 16
// baseline (speedup 1.0000x reference)
#include <cuda_runtime.h>
#include <cuda_fp16.h>
#include <cstdint>

#define BATCH 32
#define T_LEN 2048
#define S_DIM 512
#define E_DIM 32
#define SLICES 4            // CTAs per batch (cluster size)
#define COLS 128            // output columns per CTA
#define NTHREADS 512
#define TARGET_EXP 6        // keep sum(w) ~ 2^6
#define VBYTES (SLICES * 64 * 4)   // 4 slices x 256B = 1024B per consumer per step
#define ZFBYTES (SLICES * 4 * 4)   // final z: 16 fp32 partials

__device__ int g_obs[BATCH * T_LEN];

__global__ void obs_extract_kernel(const float* __restrict__ inputs) {
    int idx = blockIdx.x * blockDim.x + threadIdx.x;
    if (idx >= BATCH * T_LEN) return;
    const float* p = inputs + (size_t)idx * E_DIM;
    int e = 0;
#pragma unroll
    for (int i = 0; i < E_DIM; i++) {
        if (p[i] > 0.5f) e = i;
    }
    g_obs[idx] = e;
}

__device__ __forceinline__ uint32_t smem_u32(const void* p) {
    uint32_t a;
    asm("{ .reg .u64 t; cvta.to.shared.u64 t, %1; cvt.u32.u64 %0, t; }"
        : "=r"(a) : "l"(p));
    return a;
}

__device__ __forceinline__ uint32_t mapa_u32(uint32_t saddr, uint32_t rank) {
    uint32_t ra;
    asm("mapa.shared::cluster.u32 %0, %1, %2;" : "=r"(ra) : "r"(saddr), "r"(rank));
    return ra;
}

__device__ __forceinline__ void cluster_sync_() {
    asm volatile("barrier.cluster.arrive.aligned;" ::: "memory");
    asm volatile("barrier.cluster.wait.aligned;" ::: "memory");
}

// tx-counted async stores into (remote) cluster smem
__device__ __forceinline__ void st_async_u32(uint32_t raddr, uint32_t v, uint32_t rmbar) {
    asm volatile(
        "st.async.shared::cluster.mbarrier::complete_tx::bytes.b32 [%0], %1, [%2];"
        :: "r"(raddr), "r"(v), "r"(rmbar) : "memory");
}
__device__ __forceinline__ void st_async_u64(uint32_t raddr, uint64_t v, uint32_t rmbar) {
    asm volatile(
        "st.async.shared::cluster.mbarrier::complete_tx::bytes.b64 [%0], %1, [%2];"
        :: "r"(raddr), "l"(v), "r"(rmbar) : "memory");
}

// plain remote cluster-smem store (no mbarrier) — consumed >=1 full step later
__device__ __forceinline__ void st_cluster_f32(uint32_t raddr, float v) {
    asm volatile("st.shared::cluster.f32 [%0], %1;" :: "r"(raddr), "f"(v) : "memory");
}

__device__ __forceinline__ void mbar_init(uint32_t mbar, uint32_t cnt) {
    asm volatile("mbarrier.init.shared.b64 [%0], %1;" :: "r"(mbar), "r"(cnt) : "memory");
}

__device__ __forceinline__ void mbar_expect_tx(uint32_t mbar, uint32_t bytes) {
    asm volatile("mbarrier.arrive.expect_tx.shared.b64 _, [%0], %1;"
                 :: "r"(mbar), "r"(bytes) : "memory");
}

__device__ __forceinline__ void mbar_wait_parity(uint32_t mbar, uint32_t parity) {
    asm volatile(
        "{\n\t"
        ".reg .pred P;\n\t"
        "WAIT_%=: \n\t"
        "mbarrier.try_wait.parity.acquire.cluster.shared::cta.b64 P, [%0], %1, 0x989680;\n\t"
        "@!P bra WAIT_%=;\n\t"
        "}"
        :: "r"(mbar), "r"(parity) : "memory");
}

__device__ __forceinline__ float warp_sum32(float v) {
#pragma unroll
    for (int o = 16; o > 0; o >>= 1)
        v += __shfl_xor_sync(0xffffffffu, v, o);
    return v;
}

__global__ void __cluster_dims__(SLICES, 1, 1) __launch_bounds__(NTHREADS, 1)
hmm_forward_kernel(const float* __restrict__ A,
                   const float* __restrict__ Bem,
                   const float* __restrict__ pi,
                   float* __restrict__ out)
{
    __shared__ __align__(16) uint32_t alpha2[2][S_DIM / 2]; // packed half2
    __shared__ __align__(16) float    zbuf[4][SLICES * 4];  // lagged-Z ring
    __shared__ __align__(16) float    zfin[SLICES * 4];     // final-step exact z
    __shared__ float    bem_t[E_DIM][COLS];                 // emission transposed
    __shared__ float    part[4][COLS];                      // per-row-chunk partials
    __shared__ float    embias[E_DIM];                      // mean emission / symbol
    __shared__ int      obs_s[T_LEN];
    __shared__ __align__(8) unsigned long long mbar_store[3]; // v0, v1, zfin

    const int tid = threadIdx.x;
    const int w = tid >> 5;
    const int l = tid & 31;
    const int kc = w >> 2;      // row chunk 0..3 (128 rows each)
    const int cg = w & 3;       // col group 0..3 (32 cols each)
    uint32_t crank;
    asm("mov.u32 %0, %%cluster_ctarank;" : "=r"(crank));
    const int c = (int)crank;
    const int b = blockIdx.x / SLICES;

    const int jl_mv = cg * 32 + l;        // matvec column within slice
    const int jg_mv = c * COLS + jl_mv;   // global column

    // ---- A slice into registers (persistent fp16x2) ----
    __half2 a2[64];
#pragma unroll
    for (int p = 0; p < 64; p++) {
        float r0 = A[(size_t)(128 * kc + 2 * p) * S_DIM + jg_mv];
        float r1 = A[(size_t)(128 * kc + 2 * p + 1) * S_DIM + jg_mv];
        a2[p] = __floats2half2_rn(r0, r1);
    }

    for (int i = tid; i < E_DIM * COLS; i += NTHREADS) {
        int e = i / COLS, j = i % COLS;
        bem_t[e][j] = Bem[(size_t)(c * COLS + j) * E_DIM + e];
    }
    for (int i = tid; i < T_LEN; i += NTHREADS) obs_s[i] = g_obs[b * T_LEN + i];

    // ---- per-symbol mean emission (lagged scale estimate) ----
    {
        int e = tid >> 4, seg = tid & 15;
        float s = 0.0f;
#pragma unroll 4
        for (int i = 0; i < 32; i++)
            s += Bem[(size_t)(seg * 32 + i) * E_DIM + e];
#pragma unroll
        for (int o = 8; o > 0; o >>= 1)
            s += __shfl_xor_sync(0xffffffffu, s, o);
        if (seg == 0) embias[e] = s * (1.0f / 512.0f);
    }

    const uint32_t val_sa  = smem_u32(&alpha2[0][0]);
    const uint32_t z_sa    = smem_u32(&zbuf[0][0]);
    const uint32_t zf_sa   = smem_u32(&zfin[0]);
    const uint32_t mbar_sa = smem_u32(&mbar_store[0]);
    // mbar: v[buf] = buf*8 ; zfin = 16

    if (tid == 0) {
#pragma unroll
        for (int i = 0; i < 3; i++) mbar_init(mbar_sa + i * 8, 1);
        mbar_expect_tx(mbar_sa + 16, ZFBYTES);   // final-z expect, posted once
        mbar_expect_tx(mbar_sa + 0, VBYTES);     // buf0 expect for t=0
    }
    __syncthreads();
    cluster_sync_();   // peers' mbarriers + smem ready before any remote store

    uint32_t val_r[SLICES], z_r[SLICES], zf_r[SLICES], mb_r[SLICES];
#pragma unroll
    for (int r = 0; r < SLICES; r++) {
        val_r[r] = mapa_u32(val_sa, (uint32_t)r);
        z_r[r]   = mapa_u32(z_sa, (uint32_t)r);
        zf_r[r]  = mapa_u32(zf_sa, (uint32_t)r);
        mb_r[r]  = mapa_u32(mbar_sa, (uint32_t)r);
    }

    // ---- PROLOGUE: w_0 = 2^TARGET * pi .* em_0 -> buf 0 ; z(0) -> ring slot 0 ----
    if (tid < 128) {
        const int e0 = obs_s[0];
        float m = pi[c * COLS + tid] * bem_t[e0][tid] * (float)(1 << TARGET_EXP);
        float mh = __shfl_down_sync(0xffffffffu, m, 1);
        __half2 h = __floats2half2_rn(m, mh);
        uint32_t wlo = *reinterpret_cast<uint32_t*>(&h);
        uint32_t whi = __shfl_down_sync(0xffffffffu, wlo, 2);
        if ((l & 3) == 0) {
            uint64_t v64 = (uint64_t)wlo | ((uint64_t)whi << 32);
            uint32_t voff = (uint32_t)((c * 64 + (tid >> 1)) * 4);
#pragma unroll
            for (int r = 0; r < SLICES; r++)
                st_async_u64(val_r[r] + voff, v64, mb_r[r] + 0);
        }
        float zs = warp_sum32(m);
        if (l == 0) {
            uint32_t zoff = (uint32_t)((0 * 16 + c * 4 + w) * 4);  // ring slot 0
#pragma unroll
            for (int r = 0; r < SLICES; r++)
                st_cluster_f32(z_r[r] + zoff, zs);
        }
    }

    int K = TARGET_EXP;
    int d_prev = 0;

    for (int t = 0; t < T_LEN - 1; t++) {
        const int buf = t & 1;
        const int nbuf = buf ^ 1;
        const uint32_t par = (uint32_t)((t >> 1) & 1);

        // ---- scale compute PRE-matvec in epilogue warps (lagged Z: no wait) ----
        float scale = 0.0f;
        int en = 0;
        if (tid < 128) {
            en = obs_s[t + 1];
            float Zm;
            int dp;
            if (t == 0) {
                Zm = (float)(1 << TARGET_EXP) * embias[obs_s[0]] * embias[en];
                dp = 0;
            } else {
                const int zslot = (t - 1) & 3;
                const float4* zb = reinterpret_cast<const float4*>(&zbuf[zslot][0]);
                float4 q0 = zb[0], q1 = zb[1], q2 = zb[2], q3 = zb[3];
                float Zp = (((q0.x + q0.y) + (q0.z + q0.w)) +
                            ((q1.x + q1.y) + (q1.z + q1.w))) +
                           (((q2.x + q2.y) + (q2.z + q2.w)) +
                            ((q3.x + q3.y) + (q3.z + q3.w)));
                const int et = obs_s[t];
                Zm = Zp * embias[et] * embias[en];
                dp = d_prev;
            }
            int ex = ((__float_as_int(Zm) >> 23) & 255) - 127;
            int d = TARGET_EXP - ex - dp;
            d = d < -48 ? -48 : (d > 48 ? 48 : d);
            scale = __int_as_float((uint32_t)(d + 127) << 23);
            d_prev = d;
            K += d;
        }

        // ---- all warps: wait for values, then matvec ----
        mbar_wait_parity(mbar_sa + buf * 8, par);

        __half2 acc0 = __float2half2_rn(0.0f);
        __half2 acc1 = acc0;
        const uint32_t* ab = &alpha2[buf][64 * kc];
#pragma unroll
        for (int m2 = 0; m2 < 32; m2++) {
            uint2 av = *reinterpret_cast<const uint2*>(&ab[2 * m2]);
            acc0 = __hfma2(*reinterpret_cast<__half2*>(&av.x), a2[2 * m2], acc0);
            acc1 = __hfma2(*reinterpret_cast<__half2*>(&av.y), a2[2 * m2 + 1], acc1);
        }
        acc0 = __hadd2(acc0, acc1);
        float2 f0 = __half22float2(acc0);
        part[kc][jl_mv] = f0.x + f0.y;
        __syncthreads();

        // early expect for the NEXT buffer, posted by a NON-epilogue warp
        if (tid == 480) mbar_expect_tx(mbar_sa + nbuf * 8, VBYTES);

        // ---- epilogue (warps 0-3, 1 column each): reduce, scale, ship b64 quads ----
        if (tid < 128) {
            float s = (part[0][tid] + part[1][tid]) +
                      (part[2][tid] + part[3][tid]);
            float m = s * bem_t[en][tid] * scale;
            float mh = __shfl_down_sync(0xffffffffu, m, 1);
            __half2 h = __floats2half2_rn(m, mh);
            uint32_t wlo = *reinterpret_cast<uint32_t*>(&h);
            uint32_t whi = __shfl_down_sync(0xffffffffu, wlo, 2);
            if ((l & 3) == 0) {
                uint64_t v64 = (uint64_t)wlo | ((uint64_t)whi << 32);
                uint32_t voff = (uint32_t)((nbuf * 256 + c * 64 + (tid >> 1)) * 4);
#pragma unroll
                for (int r = 0; r < SLICES; r++)
                    st_async_u64(val_r[r] + voff, v64, mb_r[r] + nbuf * 8);
            }

            // z-partial trails the values — consumed >=1 step later
            float zs = warp_sum32(m);
            if (l == 0) {
                uint32_t zoff = (uint32_t)((((t + 1) & 3) * 16 + c * 4 + w) * 4);
#pragma unroll
                for (int r = 0; r < SLICES; r++)
                    st_cluster_f32(z_r[r] + zoff, zs);
                if (t == T_LEN - 2) {
                    uint32_t zfo = (uint32_t)((c * 4 + w) * 4);
#pragma unroll
                    for (int r = 0; r < SLICES; r++)
                        st_async_u32(zf_r[r] + zfo, __float_as_uint(zs),
                                     mb_r[r] + 16);
                }
            }
        }
    }

    // ---- FINAL: exact Z(T-1) via dedicated mbarrier ----
    mbar_wait_parity(mbar_sa + 16, 0);
    if (c == 0 && tid == 0) {
        float Z = 0.0f;
#pragma unroll
        for (int i = 0; i < SLICES * 4; i++) Z += zfin[i];
        out[b] = (log2f(Z) - (float)K) * 0.6931471805599453f;
    }
    cluster_sync_();   // no CTA exits while peers may still target its smem
}

extern "C" void kernel_launch(void* const* d_in, const int* in_sizes, int n_in,
                              void* d_out, int out_size)
{
    const float* inputs = (const float*)d_in[0];  // [B,T,E] one-hot
    const float* A      = (const float*)d_in[1];  // [S,S]
    const float* Bem    = (const float*)d_in[2];  // [S,E]
    const float* pi     = (const float*)d_in[3];  // [S]
    float* out = (float*)d_out;                   // [B]

    obs_extract_kernel<<<(BATCH * T_LEN + 255) / 256, 256>>>(inputs);
    hmm_forward_kernel<<<BATCH * SLICES, NTHREADS>>>(A, Bem, pi, out);
}

// round 17
// speedup vs baseline: 1.6433x; 1.6433x over previous
#include <cuda_runtime.h>
#include <cuda_fp16.h>
#include <cstdint>

#define BATCH 32
#define T_LEN 2048
#define S_DIM 512
#define E_DIM 32
#define SLICES 4            // CTAs per batch (cluster size)
#define COLS 128            // output columns per CTA
#define NTHREADS 512
#define TARGET_EXP 6        // keep sum(w) ~ 2^6
#define VBYTES (SLICES * 64 * 4)   // 4 slices x 64 half2 words = 1024B
#define ZFBYTES (SLICES * 4 * 4)   // final z: 16 fp32 partials

__device__ int g_obs[BATCH * T_LEN];

__global__ void obs_extract_kernel(const float* __restrict__ inputs) {
    int idx = blockIdx.x * blockDim.x + threadIdx.x;
    if (idx >= BATCH * T_LEN) return;
    const float* p = inputs + (size_t)idx * E_DIM;
    int e = 0;
#pragma unroll
    for (int i = 0; i < E_DIM; i++) {
        if (p[i] > 0.5f) e = i;
    }
    g_obs[idx] = e;
}

__device__ __forceinline__ uint32_t smem_u32(const void* p) {
    uint32_t a;
    asm("{ .reg .u64 t; cvta.to.shared.u64 t, %1; cvt.u32.u64 %0, t; }"
        : "=r"(a) : "l"(p));
    return a;
}

__device__ __forceinline__ uint32_t mapa_u32(uint32_t saddr, uint32_t rank) {
    uint32_t ra;
    asm("mapa.shared::cluster.u32 %0, %1, %2;" : "=r"(ra) : "r"(saddr), "r"(rank));
    return ra;
}

__device__ __forceinline__ void cluster_sync_() {
    asm volatile("barrier.cluster.arrive.aligned;" ::: "memory");
    asm volatile("barrier.cluster.wait.aligned;" ::: "memory");
}

// tx-counted async store (4B) into (remote) cluster smem
__device__ __forceinline__ void st_async_u32(uint32_t raddr, uint32_t v, uint32_t rmbar) {
    asm volatile(
        "st.async.shared::cluster.mbarrier::complete_tx::bytes.b32 [%0], %1, [%2];"
        :: "r"(raddr), "r"(v), "r"(rmbar) : "memory");
}

// plain remote cluster-smem store (no mbarrier) — consumed >=1 full step later
__device__ __forceinline__ void st_cluster_f32(uint32_t raddr, float v) {
    asm volatile("st.shared::cluster.f32 [%0], %1;" :: "r"(raddr), "f"(v) : "memory");
}

__device__ __forceinline__ void mbar_init(uint32_t mbar, uint32_t cnt) {
    asm volatile("mbarrier.init.shared.b64 [%0], %1;" :: "r"(mbar), "r"(cnt) : "memory");
}

__device__ __forceinline__ void mbar_expect_tx(uint32_t mbar, uint32_t bytes) {
    asm volatile("mbarrier.arrive.expect_tx.shared.b64 _, [%0], %1;"
                 :: "r"(mbar), "r"(bytes) : "memory");
}

__device__ __forceinline__ void mbar_wait_parity(uint32_t mbar, uint32_t parity) {
    asm volatile(
        "{\n\t"
        ".reg .pred P;\n\t"
        "WAIT_%=: \n\t"
        "mbarrier.try_wait.parity.acquire.cluster.shared::cta.b64 P, [%0], %1, 0x989680;\n\t"
        "@!P bra WAIT_%=;\n\t"
        "}"
        :: "r"(mbar), "r"(parity) : "memory");
}

__device__ __forceinline__ float warp_sum32(float v) {
#pragma unroll
    for (int o = 16; o > 0; o >>= 1)
        v += __shfl_xor_sync(0xffffffffu, v, o);
    return v;
}

__global__ void __cluster_dims__(SLICES, 1, 1) __launch_bounds__(NTHREADS, 1)
hmm_forward_kernel(const float* __restrict__ A,
                   const float* __restrict__ Bem,
                   const float* __restrict__ pi,
                   float* __restrict__ out)
{
    __shared__ __align__(16) uint32_t alpha2[2][S_DIM / 2]; // packed half2
    __shared__ __align__(16) float    zbuf[4][SLICES * 4];  // lagged-Z ring
    __shared__ __align__(16) float    zfin[SLICES * 4];     // final-step exact z
    __shared__ float    bem_t[E_DIM][COLS];                 // emission transposed
    __shared__ float    part[4][COLS];                      // per-row-chunk partials
    __shared__ float    embias[E_DIM];                      // mean emission / symbol
    __shared__ int      obs_s[T_LEN];
    __shared__ __align__(8) unsigned long long mbar_store[3]; // v0, v1, zfin

    const int tid = threadIdx.x;
    const int w = tid >> 5;
    const int l = tid & 31;
    const int kc = w >> 2;      // row chunk 0..3 (128 rows each)
    const int cg = w & 3;       // col group 0..3 (32 cols each)
    uint32_t crank;
    asm("mov.u32 %0, %%cluster_ctarank;" : "=r"(crank));
    const int c = (int)crank;
    const int b = blockIdx.x / SLICES;

    const int jl_mv = cg * 32 + l;        // matvec column within slice
    const int jg_mv = c * COLS + jl_mv;   // global column

    // ---- A slice into registers (persistent fp16x2) ----
    __half2 a2[64];
#pragma unroll
    for (int p = 0; p < 64; p++) {
        float r0 = A[(size_t)(128 * kc + 2 * p) * S_DIM + jg_mv];
        float r1 = A[(size_t)(128 * kc + 2 * p + 1) * S_DIM + jg_mv];
        a2[p] = __floats2half2_rn(r0, r1);
    }

    for (int i = tid; i < E_DIM * COLS; i += NTHREADS) {
        int e = i / COLS, j = i % COLS;
        bem_t[e][j] = Bem[(size_t)(c * COLS + j) * E_DIM + e];
    }
    for (int i = tid; i < T_LEN; i += NTHREADS) obs_s[i] = g_obs[b * T_LEN + i];

    // ---- per-symbol mean emission (lagged scale estimate) ----
    {
        int e = tid >> 4, seg = tid & 15;
        float s = 0.0f;
#pragma unroll 4
        for (int i = 0; i < 32; i++)
            s += Bem[(size_t)(seg * 32 + i) * E_DIM + e];
#pragma unroll
        for (int o = 8; o > 0; o >>= 1)
            s += __shfl_xor_sync(0xffffffffu, s, o);
        if (seg == 0) embias[e] = s * (1.0f / 512.0f);
    }

    const uint32_t val_sa  = smem_u32(&alpha2[0][0]);
    const uint32_t z_sa    = smem_u32(&zbuf[0][0]);
    const uint32_t zf_sa   = smem_u32(&zfin[0]);
    const uint32_t mbar_sa = smem_u32(&mbar_store[0]);
    // mbar: v[buf] = buf*8 ; zfin = 16

    if (tid == 0) {
#pragma unroll
        for (int i = 0; i < 3; i++) mbar_init(mbar_sa + i * 8, 1);
        mbar_expect_tx(mbar_sa + 16, ZFBYTES);   // final-z expect, posted once
    }
    __syncthreads();
    cluster_sync_();   // peers' mbarriers + smem ready before any remote store

    uint32_t val_r[SLICES], z_r[SLICES], zf_r[SLICES], mb_r[SLICES];
#pragma unroll
    for (int r = 0; r < SLICES; r++) {
        val_r[r] = mapa_u32(val_sa, (uint32_t)r);
        z_r[r]   = mapa_u32(z_sa, (uint32_t)r);
        zf_r[r]  = mapa_u32(zf_sa, (uint32_t)r);
        mb_r[r]  = mapa_u32(mbar_sa, (uint32_t)r);
    }

    // ---- PROLOGUE: w_0 = 2^TARGET * pi .* em_0 -> buf 0 ; z(0) -> ring slot 0 ----
    if (tid < 128) {
        const int e0 = obs_s[0];
        float m = pi[c * COLS + tid] * bem_t[e0][tid] * (float)(1 << TARGET_EXP);
        float mh = __shfl_down_sync(0xffffffffu, m, 1);
        if (!(l & 1)) {
            __half2 h = __floats2half2_rn(m, mh);
            uint32_t hv = *reinterpret_cast<uint32_t*>(&h);
            uint32_t voff = (uint32_t)((c * 64 + (tid >> 1)) * 4);
#pragma unroll
            for (int r = 0; r < SLICES; r++)
                st_async_u32(val_r[r] + voff, hv, mb_r[r] + 0);
        }
        float zs = warp_sum32(m);
        if (l == 0) {
            uint32_t zoff = (uint32_t)((0 * 16 + c * 4 + w) * 4);  // ring slot 0
#pragma unroll
            for (int r = 0; r < SLICES; r++)
                st_cluster_f32(z_r[r] + zoff, zs);
        }
    }

    int K = TARGET_EXP;
    int d_prev = 0;

    for (int t = 0; t < T_LEN - 1; t++) {
        const int buf = t & 1;
        const int nbuf = buf ^ 1;
        const uint32_t par = (uint32_t)((t >> 1) & 1);

        if (tid == 0) mbar_expect_tx(mbar_sa + buf * 8, VBYTES);

        // ---- scale compute PRE-matvec in epilogue warps (lagged Z: no wait) ----
        float scale = 0.0f;
        int en = 0;
        if (tid < 128) {
            en = obs_s[t + 1];
            float Zm;
            int dp;
            if (t == 0) {
                Zm = (float)(1 << TARGET_EXP) * embias[obs_s[0]] * embias[en];
                dp = 0;
            } else {
                const int zslot = (t - 1) & 3;
                const float4* zb = reinterpret_cast<const float4*>(&zbuf[zslot][0]);
                float4 q0 = zb[0], q1 = zb[1], q2 = zb[2], q3 = zb[3];
                float Zp = (((q0.x + q0.y) + (q0.z + q0.w)) +
                            ((q1.x + q1.y) + (q1.z + q1.w))) +
                           (((q2.x + q2.y) + (q2.z + q2.w)) +
                            ((q3.x + q3.y) + (q3.z + q3.w)));
                const int et = obs_s[t];
                Zm = Zp * embias[et] * embias[en];
                dp = d_prev;
            }
            int ex = ((__float_as_int(Zm) >> 23) & 255) - 127;
            int d = TARGET_EXP - ex - dp;
            d = d < -48 ? -48 : (d > 48 ? 48 : d);
            scale = __int_as_float((uint32_t)(d + 127) << 23);
            d_prev = d;
            K += d;
        }

        // ---- all warps: wait for values, then matvec ----
        mbar_wait_parity(mbar_sa + buf * 8, par);

        __half2 acc0 = __float2half2_rn(0.0f);
        __half2 acc1 = acc0;
        const uint32_t* ab = &alpha2[buf][64 * kc];
#pragma unroll
        for (int m2 = 0; m2 < 32; m2++) {
            uint2 av = *reinterpret_cast<const uint2*>(&ab[2 * m2]);
            acc0 = __hfma2(*reinterpret_cast<__half2*>(&av.x), a2[2 * m2], acc0);
            acc1 = __hfma2(*reinterpret_cast<__half2*>(&av.y), a2[2 * m2 + 1], acc1);
        }
        acc0 = __hadd2(acc0, acc1);
        float2 f0 = __half22float2(acc0);
        part[kc][jl_mv] = f0.x + f0.y;
        __syncthreads();

        // ---- epilogue (warps 0-3, 1 column per thread): reduce, scale, ship ----
        if (tid < 128) {
            float s = (part[0][tid] + part[1][tid]) +
                      (part[2][tid] + part[3][tid]);
            float m = s * bem_t[en][tid] * scale;
            float mh = __shfl_down_sync(0xffffffffu, m, 1);
            if (!(l & 1)) {
                __half2 h = __floats2half2_rn(m, mh);
                uint32_t hv = *reinterpret_cast<uint32_t*>(&h);
                uint32_t voff = (uint32_t)((nbuf * 256 + c * 64 + (tid >> 1)) * 4);
#pragma unroll
                for (int r = 0; r < SLICES; r++)
                    st_async_u32(val_r[r] + voff, hv, mb_r[r] + nbuf * 8);
            }

            // z-partial trails the values — consumed >=1 step later
            float zs = warp_sum32(m);
            if (l == 0) {
                uint32_t zoff = (uint32_t)((((t + 1) & 3) * 16 + c * 4 + w) * 4);
#pragma unroll
                for (int r = 0; r < SLICES; r++)
                    st_cluster_f32(z_r[r] + zoff, zs);
                if (t == T_LEN - 2) {
                    uint32_t zfo = (uint32_t)((c * 4 + w) * 4);
#pragma unroll
                    for (int r = 0; r < SLICES; r++)
                        st_async_u32(zf_r[r] + zfo, __float_as_uint(zs),
                                     mb_r[r] + 16);
                }
            }
        }
    }

    // ---- FINAL: exact Z(T-1) via dedicated mbarrier ----
    mbar_wait_parity(mbar_sa + 16, 0);
    if (c == 0 && tid == 0) {
        float Z = 0.0f;
#pragma unroll
        for (int i = 0; i < SLICES * 4; i++) Z += zfin[i];
        out[b] = (log2f(Z) - (float)K) * 0.6931471805599453f;
    }
    cluster_sync_();   // no CTA exits while peers may still target its smem
}

extern "C" void kernel_launch(void* const* d_in, const int* in_sizes, int n_in,
                              void* d_out, int out_size)
{
    const float* inputs = (const float*)d_in[0];  // [B,T,E] one-hot
    const float* A      = (const float*)d_in[1];  // [S,S]
    const float* Bem    = (const float*)d_in[2];  // [S,E]
    const float* pi     = (const float*)d_in[3];  // [S]
    float* out = (float*)d_out;                   // [B]

    obs_extract_kernel<<<(BATCH * T_LEN + 255) / 256, 256>>>(inputs);
    hmm_forward_kernel<<<BATCH * SLICES, NTHREADS>>>(A, Bem, pi, out);
}